// round 2
// baseline (speedup 1.0000x reference)
#include <cuda_runtime.h>
#include <cstdint>

#define F        128
#define TILE     128
#define LB       96
#define RCAP     (TILE + LB + 1)        // 225 window rows (row 0 = zeros)
#define NT       256
#define WIN_FLTS (RCAP * F)             // 28800
#define APM_U32  (8 * 16 * 33 * 4)      // 16896 u32 (uint4[8mt][16ks][33])
#define WB_STRIDE 136

__device__ __forceinline__ uint32_t f2tf32(float x) {
    uint32_t r;
    asm("cvt.rna.tf32.f32 %0, %1;" : "=r"(r) : "f"(x));
    return r;
}

__device__ __forceinline__ void mma8(float c[4], uint32_t a0, uint32_t a1, uint32_t a2,
                                     uint32_t a3, uint32_t b0, uint32_t b1) {
    asm volatile(
        "mma.sync.aligned.m16n8k8.row.col.f32.tf32.tf32.f32 "
        "{%0,%1,%2,%3}, {%4,%5,%6,%7}, {%8,%9}, {%0,%1,%2,%3};\n"
        : "+f"(c[0]), "+f"(c[1]), "+f"(c[2]), "+f"(c[3])
        : "r"(a0), "r"(a1), "r"(a2), "r"(a3), "r"(b0), "r"(b1));
}

// scatter 4 consecutive-col tf32 values of row rr (cols q*4..q*4+3) into fragment-permuted A
__device__ __forceinline__ void scatterA(uint32_t* Apm, int rr, int q,
                                         uint32_t v0, uint32_t v1, uint32_t v2, uint32_t v3) {
    int mt = rr >> 4, rin = rr & 15;
    int hi = rin >> 3, r8 = rin & 7;
    int ks = q >> 1, kb = q & 1;
    int slot = kb * 2 + hi;
    int b = ((mt * 16 + ks) * 33 + r8 * 4) * 4 + slot;
    Apm[b]      = v0;
    Apm[b + 4]  = v1;
    Apm[b + 8]  = v2;
    Apm[b + 12] = v3;
}

__device__ __forceinline__ void stageW(uint32_t* Wb, const float* Wg, int tid) {
    #pragma unroll
    for (int it = 0; it < 16; it++) {
        int i = tid + it * NT;              // 4096 items: 128 rows x 32 f4
        int k = i >> 5, q = i & 31;
        float4 w = reinterpret_cast<const float4*>(Wg + k * F)[q];
        uint4 u;
        u.x = f2tf32(w.x); u.y = f2tf32(w.y); u.z = f2tf32(w.z); u.w = f2tf32(w.w);
        reinterpret_cast<uint4*>(Wb)[k * (WB_STRIDE / 4) + q] = u;
    }
}

__device__ __forceinline__ void gemm_half(const uint32_t* Apm, const uint32_t* Wb,
                                          float acc[4][4][4], int lane, int wm, int wn) {
    #pragma unroll
    for (int ks = 0; ks < 16; ks++) {
        uint32_t b0[4], b1[4];
        int krow = ks * 8 + (lane & 3);
        int ncol = lane >> 2;
        #pragma unroll
        for (int nt = 0; nt < 4; nt++) {
            int n0 = wn * 32 + nt * 8;
            b0[nt] = Wb[krow * WB_STRIDE + n0 + ncol];
            b1[nt] = Wb[(krow + 4) * WB_STRIDE + n0 + ncol];
        }
        #pragma unroll
        for (int mi = 0; mi < 4; mi++) {
            uint4 a = reinterpret_cast<const uint4*>(Apm)[((wm * 4 + mi) * 16 + ks) * 33 + lane];
            #pragma unroll
            for (int nt = 0; nt < 4; nt++)
                mma8(acc[mi][nt], a.x, a.y, a.z, a.w, b0[nt], b1[nt]);
        }
    }
}

extern __shared__ float sm_f[];

__global__ void __launch_bounds__(NT, 1)
fast_tsage_kernel(const float* __restrict__ src, const float* __restrict__ dst,
                  const int* __restrict__ dme, const float* __restrict__ deg,
                  const float* __restrict__ Wself, const float* __restrict__ bself,
                  const float* __restrict__ Wneigh, const float* __restrict__ bneigh,
                  float* __restrict__ out, int E) {
    float*    win  = sm_f;                                  // region0: 28800 f (aliases Wb)
    uint32_t* Wb   = reinterpret_cast<uint32_t*>(sm_f);     // 128 x 136 u32
    uint32_t* Apm  = reinterpret_cast<uint32_t*>(sm_f + WIN_FLTS); // 16896 u32
    float*    biasm = sm_f + WIN_FLTS + APM_U32;            // 128 f

    const int tid  = threadIdx.x;
    const int wid  = tid >> 5, lane = tid & 31;
    const int wm   = wid >> 2, wn = wid & 3;
    const int t0   = blockIdx.x * TILE;

    if (tid < F) biasm[tid] = bself[tid] + bneigh[tid];

    // ---- Phase A: load src window into smem (row 0 = zeros) ----
    int base = t0 - LB; if (base < 0) base = 0;
    int end  = t0 + TILE; if (end > E) end = E;
    int R    = end - base;
    if (tid < 32) reinterpret_cast<float4*>(win)[tid] = make_float4(0.f, 0.f, 0.f, 0.f);
    for (int i = tid; i < R * 32; i += NT) {
        int r = i >> 5, q = i & 31;
        float4 v = reinterpret_cast<const float4*>(src + (size_t)(base + r) * F)[q];
        reinterpret_cast<float4*>(win + (r + 1) * F)[q] = v;
    }
    __syncthreads();

    // ---- Phase B: per-column inclusive cumsum over window rows ----
    if (tid < F) {
        float run = 0.f;
        float* p = win + F + tid;
        #pragma unroll 4
        for (int r = 0; r < R; r++) {
            run += p[r * F];
            p[r * F] = run;
        }
    }
    __syncthreads();

    // ---- Phase C: per-edge running mean -> tf32 fragment-permuted A ----
    for (int rr = wid; rr < TILE; rr += 8) {
        int e = t0 + rr;
        float4 h = make_float4(0.f, 0.f, 0.f, 0.f);
        if (e < E) {
            int   m  = dme[e];
            float dg = deg[e];
            int   s  = m - (int)dg + 1;
            float inv = 1.f / (dg + 1.f);
            if (s >= base) {
                float4 cm = reinterpret_cast<const float4*>(win + (m - base + 1) * F)[lane];
                float4 cs = reinterpret_cast<const float4*>(win + (s - base) * F)[lane];
                h.x = (cm.x - cs.x) * inv; h.y = (cm.y - cs.y) * inv;
                h.z = (cm.z - cs.z) * inv; h.w = (cm.w - cs.w) * inv;
            } else {  // slow path (lookback exceeded) — direct global sum
                float4 a = make_float4(0.f, 0.f, 0.f, 0.f);
                for (int i = s; i <= m; i++) {
                    float4 v = reinterpret_cast<const float4*>(src + (size_t)i * F)[lane];
                    a.x += v.x; a.y += v.y; a.z += v.z; a.w += v.w;
                }
                h.x = a.x * inv; h.y = a.y * inv; h.z = a.z * inv; h.w = a.w * inv;
            }
        }
        scatterA(Apm, rr, lane, f2tf32(h.x), f2tf32(h.y), f2tf32(h.z), f2tf32(h.w));
    }
    __syncthreads();

    // ---- GEMM half 1: h @ W_neigh ----
    stageW(Wb, Wneigh, tid);
    __syncthreads();

    float acc[4][4][4];
    #pragma unroll
    for (int a = 0; a < 4; a++)
        #pragma unroll
        for (int b = 0; b < 4; b++)
            #pragma unroll
            for (int c = 0; c < 4; c++) acc[a][b][c] = 0.f;

    gemm_half(Apm, Wb, acc, lane, wm, wn);
    __syncthreads();

    // ---- restage: A = dst_feat, W = W_self ----
    #pragma unroll
    for (int it = 0; it < 16; it++) {
        int i = tid + it * NT;              // 128 rows x 32 f4
        int rr = i >> 5, q = i & 31;
        int e = t0 + rr;
        float4 v = make_float4(0.f, 0.f, 0.f, 0.f);
        if (e < E) v = reinterpret_cast<const float4*>(dst + (size_t)e * F)[q];
        scatterA(Apm, rr, q, f2tf32(v.x), f2tf32(v.y), f2tf32(v.z), f2tf32(v.w));
    }
    stageW(Wb, Wself, tid);
    __syncthreads();

    // ---- GEMM half 2: dst_feat @ W_self (accumulate) ----
    gemm_half(Apm, Wb, acc, lane, wm, wn);

    // ---- Epilogue: + bias, store ----
    #pragma unroll
    for (int mi = 0; mi < 4; mi++) {
        int grow0 = t0 + wm * 64 + mi * 16 + (lane >> 2);
        #pragma unroll
        for (int nt = 0; nt < 4; nt++) {
            int col = wn * 32 + nt * 8 + 2 * (lane & 3);
            float bx = biasm[col], by = biasm[col + 1];
            if (grow0 < E) {
                float2 v0 = make_float2(acc[mi][nt][0] + bx, acc[mi][nt][1] + by);
                reinterpret_cast<float2*>(out + (size_t)grow0 * F + col)[0] = v0;
            }
            int grow1 = grow0 + 8;
            if (grow1 < E) {
                float2 v1 = make_float2(acc[mi][nt][2] + bx, acc[mi][nt][3] + by);
                reinterpret_cast<float2*>(out + (size_t)grow1 * F + col)[0] = v1;
            }
        }
    }
}

extern "C" void kernel_launch(void* const* d_in, const int* in_sizes, int n_in,
                              void* d_out, int out_size) {
    const float* src    = (const float*)d_in[0];
    const float* dst    = (const float*)d_in[1];
    // d_in[2] = dst_ids (unused: seg_start derived from dst_max_eid & dst_deg)
    const int*   dme    = (const int*)d_in[3];
    const float* deg    = (const float*)d_in[4];
    const float* Wself  = (const float*)d_in[5];
    const float* bself  = (const float*)d_in[6];
    const float* Wneigh = (const float*)d_in[7];
    const float* bneigh = (const float*)d_in[8];
    float* out = (float*)d_out;

    int E = in_sizes[0] / F;
    int nblocks = (E + TILE - 1) / TILE;
    size_t smem = (size_t)(WIN_FLTS + APM_U32 + F) * 4;  // 183,808 B

    cudaFuncSetAttribute(fast_tsage_kernel,
                         cudaFuncAttributeMaxDynamicSharedMemorySize, (int)smem);
    fast_tsage_kernel<<<nblocks, NT, smem>>>(src, dst, dme, deg, Wself, bself,
                                             Wneigh, bneigh, out, E);
}

// round 4
// speedup vs baseline: 1.6341x; 1.6341x over previous
#include <cuda_runtime.h>
#include <cuda_fp16.h>
#include <cstdint>

#define F    128
#define EMAX 500000
#define TMAX ((EMAX + 127) / 128)   // 3907 tiles

// h fragment blobs: [tile][ks(8)][mt(8)][lane(32)] x uint4 = 32KB/tile (128MB)
__device__ __align__(16) uint4 g_hf[(size_t)TMAX * 2048];
// B fragment blob: [ks(16)][nt(16)][lane(32)] x uint2 (64KB)
__device__ __align__(16) uint2 g_bf[16 * 16 * 32];
__device__ float g_bias[F];

__device__ __forceinline__ uint32_t smem_u32(const void* p) {
    uint32_t a;
    asm("{ .reg .u64 t; cvta.to.shared.u64 t, %1; cvt.u32.u64 %0, t; }" : "=r"(a) : "l"(p));
    return a;
}

__device__ __forceinline__ uint32_t h2u(__half2 h) {
    return *reinterpret_cast<uint32_t*>(&h);
}

__device__ __forceinline__ void mma16(float c[4], uint32_t a0, uint32_t a1, uint32_t a2,
                                      uint32_t a3, uint32_t b0, uint32_t b1) {
    asm volatile(
        "mma.sync.aligned.m16n8k16.row.col.f32.f16.f16.f32 "
        "{%0,%1,%2,%3}, {%4,%5,%6,%7}, {%8,%9}, {%0,%1,%2,%3};\n"
        : "+f"(c[0]), "+f"(c[1]), "+f"(c[2]), "+f"(c[3])
        : "r"(a0), "r"(a1), "r"(a2), "r"(a3), "r"(b0), "r"(b1));
}

__device__ __forceinline__ void cpa16(uint32_t sa, const void* g) {
    asm volatile("cp.async.cg.shared.global [%0], [%1], 16;\n" :: "r"(sa), "l"(g));
}
#define CP_COMMIT() asm volatile("cp.async.commit_group;" ::: "memory")
#define CP_WAIT0()  asm volatile("cp.async.wait_group 0;" ::: "memory")

// ====================== k0: weights -> B fragment blob ======================
// B frag (ks, nt): lane holds halves {(k0,k0+1)@n, (k0+8,k0+9)@n},
// k0 = ks*16 + (lane%4)*2 (global K over [Ws;Wn]), n = nt*8 + lane/4.
__global__ void k0_prep(const float* __restrict__ Ws, const float* __restrict__ Wn,
                        const float* __restrict__ bs, const float* __restrict__ bn) {
    int i = blockIdx.x * blockDim.x + threadIdx.x;
    if (i < F) g_bias[i] = bs[i] + bn[i];
    if (i >= 16 * 16 * 32) return;
    int lane = i & 31, nt = (i >> 5) & 15, ks = i >> 9;
    int k = ks * 16 + (lane & 3) * 2;
    int n = nt * 8 + (lane >> 2);
    const float* W0 = (k < F) ? (Ws + (size_t)k * F) : (Wn + (size_t)(k - F) * F);
    const float* W8 = (k + 8 < F) ? (Ws + (size_t)(k + 8) * F) : (Wn + (size_t)(k + 8 - F) * F);
    __half2 lo = __floats2half2_rn(W0[n], W0[F + n]);
    __half2 hi = __floats2half2_rn(W8[n], W8[F + n]);
    uint2 u;
    u.x = h2u(lo);
    u.y = h2u(hi);
    g_bf[i] = u;
}

// ====================== k1: aggregate -> h fragment blob ======================

#define LB   48
#define RC   (128 + LB + 1)     // 177 rows incl. zero row
#define WSTR 132                // padded row stride (floats)
#define K1_SMEM (RC * WSTR * 4 + 128 * 12)

__device__ __forceinline__ float2 hval(const float* win, const float* src,
                                       const int* smm, const int* sms, const float* smv,
                                       int row, int col, int base) {
    int   mr  = smm[row];
    int   sr  = sms[row];
    float inv = smv[row];
    float2 v = *reinterpret_cast<const float2*>(win + mr * WSTR + col);
    if (sr >= 0) {
        float2 cs = *reinterpret_cast<const float2*>(win + sr * WSTR + col);
        v.x -= cs.x; v.y -= cs.y;
    } else {  // lookback exceeded (rare): add global sum over [s, base-1]
        for (int g = base + sr; g < base; g++) {
            float2 a = *reinterpret_cast<const float2*>(src + (size_t)g * F + col);
            v.x += a.x; v.y += a.y;
        }
    }
    v.x *= inv; v.y *= inv;
    return v;
}

__global__ void __launch_bounds__(256, 2)
k1_agg(const float* __restrict__ src, const int* __restrict__ dme,
       const float* __restrict__ deg, int E) {
    extern __shared__ float sm[];
    float* win = sm;                                   // RC x WSTR
    int*   smm = reinterpret_cast<int*>(sm + RC * WSTR);
    int*   sms = smm + 128;
    float* smv = reinterpret_cast<float*>(sms + 128);

    const int tid = threadIdx.x, wid = tid >> 5, lane = tid & 31;
    const int t0 = blockIdx.x * 128;
    int base = t0 - LB; if (base < 0) base = 0;
    int end  = t0 + 128; if (end > E) end = E;
    const int R = end - base;

    if (tid < WSTR) win[tid] = 0.f;   // zero row 0 (prefix before window)

    for (int i = tid; i < R * 32; i += 256) {
        int r = i >> 5, q = i & 31;
        float4 v = reinterpret_cast<const float4*>(src + (size_t)(base + r) * F)[q];
        *reinterpret_cast<float4*>(win + (r + 1) * WSTR + q * 4) = v;
    }

    if (tid < 128) {
        int e = t0 + tid;
        int m, s; float inv;
        if (e < E) {
            m = dme[e];
            float dg = deg[e];
            s = m - (int)dg + 1;
            inv = 1.f / (dg + 1.f);
        } else { m = base - 1; s = base; inv = 0.f; }
        smm[tid] = m - base + 1;   // window row of inclusive cumsum at m
        sms[tid] = s - base;       // negative => slow path
        smv[tid] = inv;
    }
    __syncthreads();

    // per-column inclusive cumsum over window rows
    if (tid < F) {
        float run = 0.f;
        float* p = win + WSTR + tid;
        #pragma unroll 4
        for (int r = 0; r < R; r++) { run += p[r * WSTR]; p[r * WSTR] = run; }
    }
    __syncthreads();

    // write h in mma fragment layout: frag unit (mt, ks); lane -> rows rA, rA+8,
    // cols k0=(lane%4)*2 (+8) within the 16-col kstep.
    uint4* outb = g_hf + (size_t)blockIdx.x * 2048;
    for (int u = wid; u < 64; u += 8) {
        int mt = u >> 3, ks = u & 7;
        int c0 = ks * 16 + (lane & 3) * 2;
        int rA = mt * 16 + (lane >> 2), rB = rA + 8;
        float2 hA0 = hval(win, src, smm, sms, smv, rA, c0,     base);
        float2 hB0 = hval(win, src, smm, sms, smv, rB, c0,     base);
        float2 hA8 = hval(win, src, smm, sms, smv, rA, c0 + 8, base);
        float2 hB8 = hval(win, src, smm, sms, smv, rB, c0 + 8, base);
        uint4 o;
        o.x = h2u(__floats2half2_rn(hA0.x, hA0.y));
        o.y = h2u(__floats2half2_rn(hB0.x, hB0.y));
        o.z = h2u(__floats2half2_rn(hA8.x, hA8.y));
        o.w = h2u(__floats2half2_rn(hB8.x, hB8.y));
        outb[(ks * 8 + mt) * 32 + lane] = o;
    }
}

// ====================== k2: fp16 mma GEMM ======================
// out[e] = dst[e]@Ws + h[e]@Wn + bias. A = [dst_fp16 | h_fp16] (K=256).
// dst half: direct LDG+cvt (L1-cached). h half: cp.async blob -> smem -> LDS.128.

__global__ void __launch_bounds__(256, 2)
k2_gemm(const float* __restrict__ dst, float* __restrict__ out, int E) {
    extern __shared__ uint4 sh[];   // 2048 uint4 = 32KB, [ks(8)][mt(8)][lane]
    const int tid = threadIdx.x, wid = tid >> 5, lane = tid & 31;
    const int wm = wid >> 2, wn = wid & 3;
    const int t0 = blockIdx.x * 128;

    // start streaming h frag blob for this tile
    {
        uint32_t sa = smem_u32(sh);
        const uint4* g = g_hf + (size_t)blockIdx.x * 2048;
        #pragma unroll
        for (int j = 0; j < 8; j++) {
            int i = tid + j * 256;
            cpa16(sa + i * 16, g + i);
        }
        CP_COMMIT();
    }

    float acc[4][4][4];
    #pragma unroll
    for (int a = 0; a < 4; a++)
        #pragma unroll
        for (int b = 0; b < 4; b++)
            #pragma unroll
            for (int c = 0; c < 4; c++) acc[a][b][c] = 0.f;

    const int r0 = lane >> 2, c00 = (lane & 3) * 2;

    // ---- dst half: K 0..127 (overlaps with cp.async) ----
    #pragma unroll
    for (int ks = 0; ks < 8; ks++) {
        uint2 b[4];
        #pragma unroll
        for (int nt = 0; nt < 4; nt++)
            b[nt] = g_bf[(ks * 16 + wn * 4 + nt) * 32 + lane];
        #pragma unroll
        for (int mi = 0; mi < 4; mi++) {
            int rA = t0 + (wm * 4 + mi) * 16 + r0;
            int rB = rA + 8;
            rA = (rA < E) ? rA : 0;   // clamp: garbage rows never stored
            rB = (rB < E) ? rB : 0;
            const float* pA = dst + (size_t)rA * F + ks * 16 + c00;
            const float* pB = dst + (size_t)rB * F + ks * 16 + c00;
            float2 aA0 = *reinterpret_cast<const float2*>(pA);
            float2 aB0 = *reinterpret_cast<const float2*>(pB);
            float2 aA8 = *reinterpret_cast<const float2*>(pA + 8);
            float2 aB8 = *reinterpret_cast<const float2*>(pB + 8);
            uint32_t a0 = h2u(__floats2half2_rn(aA0.x, aA0.y));
            uint32_t a1 = h2u(__floats2half2_rn(aB0.x, aB0.y));
            uint32_t a2 = h2u(__floats2half2_rn(aA8.x, aA8.y));
            uint32_t a3 = h2u(__floats2half2_rn(aB8.x, aB8.y));
            #pragma unroll
            for (int nt = 0; nt < 4; nt++)
                mma16(acc[mi][nt], a0, a1, a2, a3, b[nt].x, b[nt].y);
        }
    }

    CP_WAIT0();
    __syncthreads();

    // ---- h half: K 128..255 from smem fragments ----
    #pragma unroll
    for (int ks = 0; ks < 8; ks++) {
        uint2 b[4];
        #pragma unroll
        for (int nt = 0; nt < 4; nt++)
            b[nt] = g_bf[((ks + 8) * 16 + wn * 4 + nt) * 32 + lane];
        #pragma unroll
        for (int mi = 0; mi < 4; mi++) {
            uint4 a = sh[(ks * 8 + wm * 4 + mi) * 32 + lane];
            #pragma unroll
            for (int nt = 0; nt < 4; nt++)
                mma16(acc[mi][nt], a.x, a.y, a.z, a.w, b[nt].x, b[nt].y);
        }
    }

    // ---- epilogue: +bias, store ----
    #pragma unroll
    for (int mi = 0; mi < 4; mi++) {
        int rA = t0 + (wm * 4 + mi) * 16 + r0;
        #pragma unroll
        for (int nt = 0; nt < 4; nt++) {
            int col = wn * 32 + nt * 8 + c00;
            float2 bv = *reinterpret_cast<const float2*>(g_bias + col);
            if (rA < E) {
                float2 v = make_float2(acc[mi][nt][0] + bv.x, acc[mi][nt][1] + bv.y);
                *reinterpret_cast<float2*>(out + (size_t)rA * F + col) = v;
            }
            if (rA + 8 < E) {
                float2 v = make_float2(acc[mi][nt][2] + bv.x, acc[mi][nt][3] + bv.y);
                *reinterpret_cast<float2*>(out + (size_t)(rA + 8) * F + col) = v;
            }
        }
    }
}

// ====================== launch ======================

extern "C" void kernel_launch(void* const* d_in, const int* in_sizes, int n_in,
                              void* d_out, int out_size) {
    const float* src = (const float*)d_in[0];
    const float* dst = (const float*)d_in[1];
    // d_in[2] = dst_ids (unused: seg_start derived from dst_max_eid & dst_deg)
    const int*   dme = (const int*)d_in[3];
    const float* deg = (const float*)d_in[4];
    const float* Ws  = (const float*)d_in[5];
    const float* bs  = (const float*)d_in[6];
    const float* Wn  = (const float*)d_in[7];
    const float* bn  = (const float*)d_in[8];
    float* out = (float*)d_out;

    int E = in_sizes[0] / F;
    int tiles = (E + 127) >> 7;
    if (tiles > TMAX) tiles = TMAX;

    k0_prep<<<32, 256>>>(Ws, Wn, bs, bn);

    cudaFuncSetAttribute(k1_agg, cudaFuncAttributeMaxDynamicSharedMemorySize, K1_SMEM);
    k1_agg<<<tiles, 256, K1_SMEM>>>(src, dme, deg, E);

    k2_gemm<<<tiles, 256, 2048 * sizeof(uint4)>>>(dst, out, E);
}